// round 9
// baseline (speedup 1.0000x reference)
#include <cuda_runtime.h>

#define BB 32
#define CC 256
#define LL 64
#define NHKD 16
#define QKV_CH 48

// scratch (device globals; no allocations)
__device__ __align__(16) float g_xh[BB*CC*LL];        // mean over W : [b][c][h]
__device__ __align__(16) float g_xw[BB*CC*LL];        // mean over H : [b][c][w]
__device__ __align__(16) float g_att[BB*2*NHKD*LL];   // axial attention outputs
__device__ __align__(16) float g_mean[BB*2*NHKD];     // per-(b,axis) channel means
__device__ __align__(16) float g_P[BB*CC*LL];         // (A*fs+fsh)*g*0.1
__device__ __align__(16) float g_Q[BB*CC*LL];         // (B*fs)*g*0.1

// ---------------------------------------------------------------------------
// K1: per-(b,c) 64x64 tile -> row means (over W) and col means (over H).
// All 4 LDG.128 batched FIRST (MLP=4) — the R8 version had a dependent
// shfl chain between loads (MLP=1, ~4x577cyc serial => ~50us kernel).
// ---------------------------------------------------------------------------
__global__ void k1_reduce(const float* __restrict__ x) {
    int bc = blockIdx.x;                       // b*256 + c
    const float4* xt = (const float4*)(x + (size_t)bc * 4096);
    int t = threadIdx.x;                       // 256 threads
    __shared__ float scol[64];
    if (t < 64) scol[t] = 0.f;
    __syncthreads();

    // ---- batched independent loads: MLP = 4 ----
    float4 v0 = xt[t];
    float4 v1 = xt[t + 256];
    float4 v2 = xt[t + 512];
    float4 v3 = xt[t + 768];

    // ---- column partials (cols 4*(t&15)+k; same cols for all 4 vectors) ----
    float c0 = v0.x + v1.x + v2.x + v3.x;
    float c1 = v0.y + v1.y + v2.y + v3.y;
    float c2 = v0.z + v1.z + v2.z + v3.z;
    float c3 = v0.w + v1.w + v2.w + v3.w;
    c0 += __shfl_xor_sync(0xffffffffu, c0, 16);
    c1 += __shfl_xor_sync(0xffffffffu, c1, 16);
    c2 += __shfl_xor_sync(0xffffffffu, c2, 16);
    c3 += __shfl_xor_sync(0xffffffffu, c3, 16);
    if ((t & 31) < 16) {
        int cb = (t & 15) * 4;
        atomicAdd(&scol[cb + 0], c0);
        atomicAdd(&scol[cb + 1], c1);
        atomicAdd(&scol[cb + 2], c2);
        atomicAdd(&scol[cb + 3], c3);
    }

    // ---- row sums: 4 independent shfl chains (ILP) ----
    float r0 = v0.x + v0.y + v0.z + v0.w;
    float r1 = v1.x + v1.y + v1.z + v1.w;
    float r2 = v2.x + v2.y + v2.z + v2.w;
    float r3 = v3.x + v3.y + v3.z + v3.w;
    #pragma unroll
    for (int off = 8; off >= 1; off >>= 1) {
        r0 += __shfl_xor_sync(0xffffffffu, r0, off);
        r1 += __shfl_xor_sync(0xffffffffu, r1, off);
        r2 += __shfl_xor_sync(0xffffffffu, r2, off);
        r3 += __shfl_xor_sync(0xffffffffu, r3, off);
    }
    if ((t & 15) == 0) {
        int base = bc * 64;
        g_xh[base + ((t)       >> 4)] = r0 * (1.f / 64.f);
        g_xh[base + ((t + 256) >> 4)] = r1 * (1.f / 64.f);
        g_xh[base + ((t + 512) >> 4)] = r2 * (1.f / 64.f);
        g_xh[base + ((t + 768) >> 4)] = r3 * (1.f / 64.f);
    }
    __syncthreads();
    if (t < 64) g_xw[bc * 64 + t] = scol[t] * (1.f / 64.f);
}

// ---------------------------------------------------------------------------
// K23: fused qkv projection + axial attention + channel means.
// 64 blocks (b*2+axis), 256 threads. Weights staged transposed (R6 win).
// ---------------------------------------------------------------------------
__global__ void k23_qkv_attn(const float* __restrict__ w_qkv,
                             const float* __restrict__ qs,
                             const float* __restrict__ qsh,
                             const float* __restrict__ pos_h,
                             const float* __restrict__ pos_w) {
    int blk  = blockIdx.x;         // b*2+axis in [0,64)
    int axis = blk & 1;
    int b    = blk >> 1;
    const float* xm = (axis == 0 ? g_xh : g_xw) + b * CC * 64;

    __shared__ __align__(16) float swT[64][QKV_CH];  // 12 KB [cl][o]
    __shared__ float sx[64][64];                     // 16 KB [c_local][l]
    __shared__ float sT[64][53];                     // 13.3 KB qkv^T [l][o]
    __shared__ float sM[NHKD][64];                   // 4 KB attention out

    int t  = threadIdx.x;
    int l  = t & 63;
    int og = t >> 6;                   // 4 o-groups of 12

    float acc[12];
    #pragma unroll
    for (int j = 0; j < 12; ++j) acc[j] = 0.f;

    for (int cc = 0; cc < 256; cc += 64) {
        for (int e = t; e < QKV_CH * 64; e += 256) {
            int o = e >> 6, cl = e & 63;
            swT[cl][o] = w_qkv[o * 256 + cc + cl];
        }
        for (int e = t; e < 64 * 64; e += 256) {
            int cl = e >> 6, ll = e & 63;
            sx[cl][ll] = xm[(cc + cl) * 64 + ll];
        }
        __syncthreads();
        const float4* swT4 = (const float4*)swT;     // 12 float4 per row
        #pragma unroll 4
        for (int cl = 0; cl < 64; ++cl) {
            float xv = sx[cl][l];
            float4 w0 = swT4[cl * 12 + og * 3 + 0];  // warp-uniform broadcast
            float4 w1 = swT4[cl * 12 + og * 3 + 1];
            float4 w2 = swT4[cl * 12 + og * 3 + 2];
            acc[0] += w0.x * xv; acc[1]  += w0.y * xv;
            acc[2] += w0.z * xv; acc[3]  += w0.w * xv;
            acc[4] += w1.x * xv; acc[5]  += w1.y * xv;
            acc[6] += w1.z * xv; acc[7]  += w1.w * xv;
            acc[8] += w2.x * xv; acc[9]  += w2.y * xv;
            acc[10]+= w2.z * xv; acc[11] += w2.w * xv;
        }
        __syncthreads();
    }

    const float* pos = axis ? pos_w : pos_h;
    #pragma unroll
    for (int j = 0; j < 12; ++j) {
        int o = og * 12 + j;
        float v = acc[j] * qs[o] + qsh[o];
        if (o < 32) v += pos[(o & 15) * 64 + l];   // pos added to q and k
        sT[l][o] = v;
    }
    __syncthreads();

    // ---- attention (threads 0..127: i = t&63, head = t>>6) ----
    if (t < 128) {
        int i  = t & 63;
        int qo = (t >> 6) * 8;

        float qreg[8];
        #pragma unroll
        for (int d = 0; d < 8; ++d) qreg[d] = sT[i][qo + d];

        float a[64];
        float m = -1e30f;
        #pragma unroll
        for (int j = 0; j < 64; ++j) {
            float s = 0.f;
            #pragma unroll
            for (int d = 0; d < 8; ++d) s += qreg[d] * sT[j][16 + qo + d];
            s *= 0.35355339059327373f;  // 8^-0.5
            a[j] = s;
            m = fmaxf(m, s);
        }
        float ssum = 0.f;
        #pragma unroll
        for (int j = 0; j < 64; ++j) {
            float e = __expf(a[j] - m);
            a[j] = e;
            ssum += e;
        }
        float inv = 1.f / ssum;

        float acc2[8] = {0.f, 0.f, 0.f, 0.f, 0.f, 0.f, 0.f, 0.f};
        #pragma unroll
        for (int j = 0; j < 64; ++j) {
            float aj = a[j];
            #pragma unroll
            for (int d = 0; d < 8; ++d) acc2[d] += aj * sT[j][32 + qo + d];
        }
        #pragma unroll
        for (int d = 0; d < 8; ++d) {
            float v = acc2[d] * inv;
            g_att[blk * NHKD * 64 + (qo + d) * 64 + i] = v;
            sM[qo + d][i] = v;
        }
    }
    __syncthreads();

    // ---- channel means (free here; kills k45's serial stage-1) ----
    {
        int ch = t >> 4, sub = t & 15;          // 16 ch x 16 threads
        float s = 0.f;
        #pragma unroll
        for (int k = 0; k < 4; ++k) s += sM[ch][sub + 16 * k];
        #pragma unroll
        for (int off = 8; off >= 1; off >>= 1)
            s += __shfl_xor_sync(0xffffffffu, s, off);
        if (sub == 0) g_mean[blk * NHKD + ch] = s * (1.f / 64.f);
    }
}

// ---------------------------------------------------------------------------
// K45: SE gate + P/Q. 64 blocks (b,axis): gate chain duplicated per axis.
// w_fusion prefetched to padded smem (conflict-free, latency overlapped).
// ---------------------------------------------------------------------------
__global__ void k45_gate_pq(const float* __restrict__ w_fusion,
                            const float* __restrict__ fs,
                            const float* __restrict__ fsh,
                            const float* __restrict__ wg1,
                            const float* __restrict__ g1s,
                            const float* __restrict__ g1sh,
                            const float* __restrict__ wg2,
                            const float* __restrict__ g2s,
                            const float* __restrict__ g2sh) {
    int blk  = blockIdx.x;        // b*2+axis
    int axis = blk & 1;
    int b    = blk >> 1;
    int t = threadIdx.x;
    int lane = t & 31, wrp = t >> 5;       // 8 warps

    __shared__ float swf[256][33];         // 33.8 KB padded w_fusion
    __shared__ float satt[NHKD * 64];      // 4 KB this axis' attention out
    __shared__ float meanf[32];
    __shared__ float y[256];
    __shared__ float t1[64];

    // prefetch (all independent; overlap DRAM latency)
    #pragma unroll
    for (int e = t; e < 256 * 32; e += 256)
        swf[e >> 5][e & 31] = w_fusion[e];
    {
        const float4* src = (const float4*)(g_att + blk * NHKD * 64);
        ((float4*)satt)[t] = src[t];       // 256 float4 = 1024 floats
    }
    if (t < 32) meanf[t] = g_mean[b * 32 + t];   // [h 16ch | w 16ch]
    __syncthreads();

    // stage 2: y = cbn(w_fusion @ meanf)  (smem weights, conflict-free)
    {
        float s = 0.f;
        #pragma unroll
        for (int c = 0; c < 32; ++c) s += swf[t][c] * meanf[c];
        y[t] = s * fs[t] + fsh[t];
    }
    __syncthreads();

    // stage 3: t1 = silu(cbn(wg1 @ y)) — warp-per-row, coalesced lanes
    #pragma unroll
    for (int o = wrp; o < 64; o += 8) {
        const float* r = wg1 + o * 256;
        float s = 0.f;
        #pragma unroll
        for (int i = 0; i < 8; ++i) {
            int c = lane + 32 * i;
            s += r[c] * y[c];
        }
        #pragma unroll
        for (int off = 16; off >= 1; off >>= 1)
            s += __shfl_xor_sync(0xffffffffu, s, off);
        if (lane == 0) {
            s = s * g1s[o] + g1sh[o];
            t1[o] = s / (1.f + __expf(-s));
        }
    }
    __syncthreads();

    // stage 4: gate = sigmoid(cbn(wg2 @ t1))
    float gate;
    {
        const float4* wr = (const float4*)(wg2 + t * 64);
        float s = 0.f;
        #pragma unroll
        for (int c4 = 0; c4 < 16; ++c4) {
            float4 wv = wr[c4];
            s += wv.x * t1[c4 * 4 + 0] + wv.y * t1[c4 * 4 + 1]
               + wv.z * t1[c4 * 4 + 2] + wv.w * t1[c4 * 4 + 3];
        }
        s = s * g2s[t] + g2sh[t];
        gate = 1.f / (1.f + __expf(-s));
    }

    // stage 5: this axis' P or Q row for o = t
    int o = t;
    float scale = fs[o] * gate * 0.1f;
    float bias  = axis ? 0.f : fsh[o] * gate * 0.1f;
    float w[16];
    #pragma unroll
    for (int c = 0; c < 16; ++c) w[c] = swf[o][axis * 16 + c];
    float* dst = (axis ? g_Q : g_P) + (b * 256 + o) * 64;
    const float4* base = (const float4*)satt;

    #pragma unroll
    for (int lg = 0; lg < 16; ++lg) {
        float4 acc = {0.f, 0.f, 0.f, 0.f};
        #pragma unroll
        for (int c = 0; c < 16; ++c) {
            float4 xv = base[c * 16 + lg];     // warp-uniform broadcast
            acc.x += w[c] * xv.x; acc.y += w[c] * xv.y;
            acc.z += w[c] * xv.z; acc.w += w[c] * xv.w;
        }
        float4 r;
        r.x = acc.x * scale + bias; r.y = acc.y * scale + bias;
        r.z = acc.z * scale + bias; r.w = acc.w * scale + bias;
        ((float4*)dst)[lg] = r;
    }
}

// ---------------------------------------------------------------------------
// K6: out[b,o,h,w] = x + P[b,o,h] + Q[b,o,w].  8192 blocks (b,o), 256 threads.
// ---------------------------------------------------------------------------
__global__ void k6_final(const float* __restrict__ x, float* __restrict__ out) {
    int blk = blockIdx.x;              // b*256+o
    __shared__ float  sp[64];
    __shared__ float4 sq4[16];
    int t = threadIdx.x;
    if (t < 64) sp[t] = g_P[blk * 64 + t];
    else if (t < 80) sq4[t - 64] = ((const float4*)(g_Q + blk * 64))[t - 64];
    __syncthreads();

    const float4* xi = (const float4*)(x + (size_t)blk * 4096);
    float4*       xo = (float4*)(out + (size_t)blk * 4096);
    #pragma unroll
    for (int i = 0; i < 4; ++i) {
        int j = t + 256 * i;
        float  p  = sp[j >> 4];
        float4 qv = sq4[j & 15];
        float4 xv = xi[j];
        float4 r;
        r.x = xv.x + p + qv.x;
        r.y = xv.y + p + qv.y;
        r.z = xv.z + p + qv.z;
        r.w = xv.w + p + qv.w;
        xo[j] = r;
    }
}

// ---------------------------------------------------------------------------
// Input identification by element count (robust to metadata ordering).
// ---------------------------------------------------------------------------
extern "C" void kernel_launch(void* const* d_in, const int* in_sizes, int n_in,
                              void* d_out, int out_size) {
    const float *x = 0, *w_qkv = 0, *qkv_scale = 0, *qkv_shift = 0;
    const float *pos_h = 0, *pos_w = 0, *w_fusion = 0;
    const float *fusion_scale = 0, *fusion_shift = 0;
    const float *w_g1 = 0, *g1_scale = 0, *g1_shift = 0;
    const float *w_g2 = 0, *g2_scale = 0, *g2_shift = 0;

    int n48 = 0, n64 = 0, n256 = 0, n1024 = 0, n16384 = 0;
    for (int i = 0; i < n_in; ++i) {
        const float* p = (const float*)d_in[i];
        switch (in_sizes[i]) {
            case 33554432: x = p; break;
            case 12288:    w_qkv = p; break;
            case 8192:     w_fusion = p; break;
            case 48:
                if (n48++ == 0) qkv_scale = p; else qkv_shift = p; break;
            case 1024:
                if (n1024++ == 0) pos_h = p; else pos_w = p; break;
            case 16384:
                if (n16384++ == 0) w_g1 = p; else w_g2 = p; break;
            case 64:
                if (n64++ == 0) g1_scale = p; else g1_shift = p; break;
            case 256:
                switch (n256++) {
                    case 0: fusion_scale = p; break;
                    case 1: fusion_shift = p; break;
                    case 2: g2_scale = p; break;
                    default: g2_shift = p; break;
                }
                break;
            default: break;
        }
    }
    float* out = (float*)d_out;

    k1_reduce<<<BB * CC, 256>>>(x);
    k23_qkv_attn<<<64, 256>>>(w_qkv, qkv_scale, qkv_shift, pos_h, pos_w);
    k45_gate_pq<<<64, 256>>>(w_fusion, fusion_scale, fusion_shift,
                             w_g1, g1_scale, g1_shift,
                             w_g2, g2_scale, g2_shift);
    k6_final<<<BB * CC, 256>>>(x, out);
}

// round 10
// speedup vs baseline: 1.0410x; 1.0410x over previous
#include <cuda_runtime.h>

#define BB 32
#define CC 256
#define LL 64
#define NHKD 16
#define QKV_CH 48

// scratch (device globals; no allocations)
__device__ __align__(16) float g_xh[BB*CC*LL];        // mean over W : [b][c][h]
__device__ __align__(16) float g_xw[BB*CC*LL];        // mean over H : [b][c][w]
__device__ __align__(16) float g_att[BB*2*NHKD*LL];   // axial attention outputs
__device__ __align__(16) float g_mean[BB*2*NHKD];     // per-(b,axis) channel means
__device__ __align__(16) float g_P[BB*CC*LL];         // (A*fs+fsh)*g*0.1
__device__ __align__(16) float g_Q[BB*CC*LL];         // (B*fs)*g*0.1

// ---------------------------------------------------------------------------
// K1: per-(b,c) 64x64 tile -> row means (over W) and col means (over H)
// (R8 form — R9 restructure measured neutral/negative; reverted)
// ---------------------------------------------------------------------------
__global__ void k1_reduce(const float* __restrict__ x) {
    int bc = blockIdx.x;                       // b*256 + c
    const float4* xt = (const float4*)(x + (size_t)bc * 4096);
    int t = threadIdx.x;                       // 256 threads
    __shared__ float scol[64];
    if (t < 64) scol[t] = 0.f;
    __syncthreads();

    float c0 = 0.f, c1 = 0.f, c2 = 0.f, c3 = 0.f;
    #pragma unroll
    for (int i = 0; i < 4; ++i) {
        int j = t + 256 * i;                   // float4 index in [0,1024)
        float4 v = xt[j];
        float rs = v.x + v.y + v.z + v.w;
        #pragma unroll
        for (int off = 8; off >= 1; off >>= 1)
            rs += __shfl_xor_sync(0xffffffffu, rs, off);
        if ((t & 15) == 0)
            g_xh[bc * 64 + (j >> 4)] = rs * (1.f / 64.f);
        c0 += v.x; c1 += v.y; c2 += v.z; c3 += v.w;
    }
    c0 += __shfl_xor_sync(0xffffffffu, c0, 16);
    c1 += __shfl_xor_sync(0xffffffffu, c1, 16);
    c2 += __shfl_xor_sync(0xffffffffu, c2, 16);
    c3 += __shfl_xor_sync(0xffffffffu, c3, 16);
    if ((t & 31) < 16) {
        int cb = (t & 15) * 4;
        atomicAdd(&scol[cb + 0], c0);
        atomicAdd(&scol[cb + 1], c1);
        atomicAdd(&scol[cb + 2], c2);
        atomicAdd(&scol[cb + 3], c3);
    }
    __syncthreads();
    if (t < 64) g_xw[bc * 64 + t] = scol[t] * (1.f / 64.f);
}

// ---------------------------------------------------------------------------
// K23: fused qkv projection + axial attention + channel means.
// 64 blocks (b*2+axis), 256 threads. Weights staged transposed (R6 win).
// ---------------------------------------------------------------------------
__global__ void k23_qkv_attn(const float* __restrict__ w_qkv,
                             const float* __restrict__ qs,
                             const float* __restrict__ qsh,
                             const float* __restrict__ pos_h,
                             const float* __restrict__ pos_w) {
    int blk  = blockIdx.x;         // b*2+axis in [0,64)
    int axis = blk & 1;
    int b    = blk >> 1;
    const float* xm = (axis == 0 ? g_xh : g_xw) + b * CC * 64;

    __shared__ __align__(16) float swT[64][QKV_CH];  // 12 KB [cl][o]
    __shared__ float sx[64][64];                     // 16 KB [c_local][l]
    __shared__ float sT[64][53];                     // 13.3 KB qkv^T [l][o]
    __shared__ float sM[NHKD][64];                   // 4 KB attention out

    int t  = threadIdx.x;
    int l  = t & 63;
    int og = t >> 6;                   // 4 o-groups of 12

    float acc[12];
    #pragma unroll
    for (int j = 0; j < 12; ++j) acc[j] = 0.f;

    for (int cc = 0; cc < 256; cc += 64) {
        for (int e = t; e < QKV_CH * 64; e += 256) {
            int o = e >> 6, cl = e & 63;
            swT[cl][o] = w_qkv[o * 256 + cc + cl];
        }
        for (int e = t; e < 64 * 64; e += 256) {
            int cl = e >> 6, ll = e & 63;
            sx[cl][ll] = xm[(cc + cl) * 64 + ll];
        }
        __syncthreads();
        const float4* swT4 = (const float4*)swT;     // 12 float4 per row
        #pragma unroll 4
        for (int cl = 0; cl < 64; ++cl) {
            float xv = sx[cl][l];
            float4 w0 = swT4[cl * 12 + og * 3 + 0];  // warp-uniform broadcast
            float4 w1 = swT4[cl * 12 + og * 3 + 1];
            float4 w2 = swT4[cl * 12 + og * 3 + 2];
            acc[0] += w0.x * xv; acc[1]  += w0.y * xv;
            acc[2] += w0.z * xv; acc[3]  += w0.w * xv;
            acc[4] += w1.x * xv; acc[5]  += w1.y * xv;
            acc[6] += w1.z * xv; acc[7]  += w1.w * xv;
            acc[8] += w2.x * xv; acc[9]  += w2.y * xv;
            acc[10]+= w2.z * xv; acc[11] += w2.w * xv;
        }
        __syncthreads();
    }

    const float* pos = axis ? pos_w : pos_h;
    #pragma unroll
    for (int j = 0; j < 12; ++j) {
        int o = og * 12 + j;
        float v = acc[j] * qs[o] + qsh[o];
        if (o < 32) v += pos[(o & 15) * 64 + l];   // pos added to q and k
        sT[l][o] = v;
    }
    __syncthreads();

    // ---- attention (threads 0..127: i = t&63, head = t>>6) ----
    if (t < 128) {
        int i  = t & 63;
        int qo = (t >> 6) * 8;

        float qreg[8];
        #pragma unroll
        for (int d = 0; d < 8; ++d) qreg[d] = sT[i][qo + d];

        float a[64];
        float m = -1e30f;
        #pragma unroll
        for (int j = 0; j < 64; ++j) {
            float s = 0.f;
            #pragma unroll
            for (int d = 0; d < 8; ++d) s += qreg[d] * sT[j][16 + qo + d];
            s *= 0.35355339059327373f;  // 8^-0.5
            a[j] = s;
            m = fmaxf(m, s);
        }
        float ssum = 0.f;
        #pragma unroll
        for (int j = 0; j < 64; ++j) {
            float e = __expf(a[j] - m);
            a[j] = e;
            ssum += e;
        }
        float inv = 1.f / ssum;

        float acc2[8] = {0.f, 0.f, 0.f, 0.f, 0.f, 0.f, 0.f, 0.f};
        #pragma unroll
        for (int j = 0; j < 64; ++j) {
            float aj = a[j];
            #pragma unroll
            for (int d = 0; d < 8; ++d) acc2[d] += aj * sT[j][32 + qo + d];
        }
        #pragma unroll
        for (int d = 0; d < 8; ++d) {
            float v = acc2[d] * inv;
            g_att[blk * NHKD * 64 + (qo + d) * 64 + i] = v;
            sM[qo + d][i] = v;
        }
    }
    __syncthreads();

    // ---- channel means (free here; kills k45's serial stage-1) ----
    {
        int ch = t >> 4, sub = t & 15;          // 16 ch x 16 threads
        float s = 0.f;
        #pragma unroll
        for (int k = 0; k < 4; ++k) s += sM[ch][sub + 16 * k];
        #pragma unroll
        for (int off = 8; off >= 1; off >>= 1)
            s += __shfl_xor_sync(0xffffffffu, s, off);
        if (sub == 0) g_mean[blk * NHKD + ch] = s * (1.f / 64.f);
    }
}

// ---------------------------------------------------------------------------
// K45: SE gate + P/Q. 64 blocks (b,axis): gate chain duplicated per axis.
// w_fusion prefetched to padded smem (conflict-free, latency overlapped).
// ---------------------------------------------------------------------------
__global__ void k45_gate_pq(const float* __restrict__ w_fusion,
                            const float* __restrict__ fs,
                            const float* __restrict__ fsh,
                            const float* __restrict__ wg1,
                            const float* __restrict__ g1s,
                            const float* __restrict__ g1sh,
                            const float* __restrict__ wg2,
                            const float* __restrict__ g2s,
                            const float* __restrict__ g2sh) {
    int blk  = blockIdx.x;        // b*2+axis
    int axis = blk & 1;
    int b    = blk >> 1;
    int t = threadIdx.x;
    int lane = t & 31, wrp = t >> 5;       // 8 warps

    __shared__ float swf[256][33];         // 33.8 KB padded w_fusion
    __shared__ float satt[NHKD * 64];      // 4 KB this axis' attention out
    __shared__ float meanf[32];
    __shared__ float y[256];
    __shared__ float t1[64];

    // prefetch (all independent; overlap DRAM latency)
    #pragma unroll
    for (int e = t; e < 256 * 32; e += 256)
        swf[e >> 5][e & 31] = w_fusion[e];
    {
        const float4* src = (const float4*)(g_att + blk * NHKD * 64);
        ((float4*)satt)[t] = src[t];       // 256 float4 = 1024 floats
    }
    if (t < 32) meanf[t] = g_mean[b * 32 + t];   // [h 16ch | w 16ch]
    __syncthreads();

    // stage 2: y = cbn(w_fusion @ meanf)  (smem weights, conflict-free)
    {
        float s = 0.f;
        #pragma unroll
        for (int c = 0; c < 32; ++c) s += swf[t][c] * meanf[c];
        y[t] = s * fs[t] + fsh[t];
    }
    __syncthreads();

    // stage 3: t1 = silu(cbn(wg1 @ y)) — warp-per-row, coalesced lanes
    #pragma unroll
    for (int o = wrp; o < 64; o += 8) {
        const float* r = wg1 + o * 256;
        float s = 0.f;
        #pragma unroll
        for (int i = 0; i < 8; ++i) {
            int c = lane + 32 * i;
            s += r[c] * y[c];
        }
        #pragma unroll
        for (int off = 16; off >= 1; off >>= 1)
            s += __shfl_xor_sync(0xffffffffu, s, off);
        if (lane == 0) {
            s = s * g1s[o] + g1sh[o];
            t1[o] = s / (1.f + __expf(-s));
        }
    }
    __syncthreads();

    // stage 4: gate = sigmoid(cbn(wg2 @ t1))
    float gate;
    {
        const float4* wr = (const float4*)(wg2 + t * 64);
        float s = 0.f;
        #pragma unroll
        for (int c4 = 0; c4 < 16; ++c4) {
            float4 wv = wr[c4];
            s += wv.x * t1[c4 * 4 + 0] + wv.y * t1[c4 * 4 + 1]
               + wv.z * t1[c4 * 4 + 2] + wv.w * t1[c4 * 4 + 3];
        }
        s = s * g2s[t] + g2sh[t];
        gate = 1.f / (1.f + __expf(-s));
    }

    // stage 5: this axis' P or Q row for o = t
    int o = t;
    float scale = fs[o] * gate * 0.1f;
    float bias  = axis ? 0.f : fsh[o] * gate * 0.1f;
    float w[16];
    #pragma unroll
    for (int c = 0; c < 16; ++c) w[c] = swf[o][axis * 16 + c];
    float* dst = (axis ? g_Q : g_P) + (b * 256 + o) * 64;
    const float4* base = (const float4*)satt;

    #pragma unroll
    for (int lg = 0; lg < 16; ++lg) {
        float4 acc = {0.f, 0.f, 0.f, 0.f};
        #pragma unroll
        for (int c = 0; c < 16; ++c) {
            float4 xv = base[c * 16 + lg];     // warp-uniform broadcast
            acc.x += w[c] * xv.x; acc.y += w[c] * xv.y;
            acc.z += w[c] * xv.z; acc.w += w[c] * xv.w;
        }
        float4 r;
        r.x = acc.x * scale + bias; r.y = acc.y * scale + bias;
        r.z = acc.z * scale + bias; r.w = acc.w * scale + bias;
        ((float4*)dst)[lg] = r;
    }
}

// ---------------------------------------------------------------------------
// K6: out[b,o,h,w] = x + P[b,o,h] + Q[b,o,w].  8192 blocks, 256 threads.
// REVERSED tile order: k1 streamed x forward through L2; reading x backward
// starts on the tiles k1 touched last (still L2-resident) instead of the
// LRU-pathological forward re-read.
// ---------------------------------------------------------------------------
__global__ void k6_final(const float* __restrict__ x, float* __restrict__ out) {
    int blk = 8191 - blockIdx.x;       // reverse: b*256+o from the tail
    __shared__ float  sp[64];
    __shared__ float4 sq4[16];
    int t = threadIdx.x;
    if (t < 64) sp[t] = g_P[blk * 64 + t];
    else if (t < 80) sq4[t - 64] = ((const float4*)(g_Q + blk * 64))[t - 64];
    __syncthreads();

    const float4* xi = (const float4*)(x + (size_t)blk * 4096);
    float4*       xo = (float4*)(out + (size_t)blk * 4096);
    #pragma unroll
    for (int i = 0; i < 4; ++i) {
        int j = t + 256 * i;
        float  p  = sp[j >> 4];
        float4 qv = sq4[j & 15];
        float4 xv = xi[j];
        float4 r;
        r.x = xv.x + p + qv.x;
        r.y = xv.y + p + qv.y;
        r.z = xv.z + p + qv.z;
        r.w = xv.w + p + qv.w;
        xo[j] = r;
    }
}

// ---------------------------------------------------------------------------
// Input identification by element count (robust to metadata ordering).
// ---------------------------------------------------------------------------
extern "C" void kernel_launch(void* const* d_in, const int* in_sizes, int n_in,
                              void* d_out, int out_size) {
    const float *x = 0, *w_qkv = 0, *qkv_scale = 0, *qkv_shift = 0;
    const float *pos_h = 0, *pos_w = 0, *w_fusion = 0;
    const float *fusion_scale = 0, *fusion_shift = 0;
    const float *w_g1 = 0, *g1_scale = 0, *g1_shift = 0;
    const float *w_g2 = 0, *g2_scale = 0, *g2_shift = 0;

    int n48 = 0, n64 = 0, n256 = 0, n1024 = 0, n16384 = 0;
    for (int i = 0; i < n_in; ++i) {
        const float* p = (const float*)d_in[i];
        switch (in_sizes[i]) {
            case 33554432: x = p; break;
            case 12288:    w_qkv = p; break;
            case 8192:     w_fusion = p; break;
            case 48:
                if (n48++ == 0) qkv_scale = p; else qkv_shift = p; break;
            case 1024:
                if (n1024++ == 0) pos_h = p; else pos_w = p; break;
            case 16384:
                if (n16384++ == 0) w_g1 = p; else w_g2 = p; break;
            case 64:
                if (n64++ == 0) g1_scale = p; else g1_shift = p; break;
            case 256:
                switch (n256++) {
                    case 0: fusion_scale = p; break;
                    case 1: fusion_shift = p; break;
                    case 2: g2_scale = p; break;
                    default: g2_shift = p; break;
                }
                break;
            default: break;
        }
    }
    float* out = (float*)d_out;

    k1_reduce<<<BB * CC, 256>>>(x);
    k23_qkv_attn<<<64, 256>>>(w_qkv, qkv_scale, qkv_shift, pos_h, pos_w);
    k45_gate_pq<<<64, 256>>>(w_fusion, fusion_scale, fusion_shift,
                             w_g1, g1_scale, g1_shift,
                             w_g2, g2_scale, g2_shift);
    k6_final<<<BB * CC, 256>>>(x, out);
}

// round 11
// speedup vs baseline: 1.0790x; 1.0365x over previous
#include <cuda_runtime.h>

#define BB 32
#define CC 256
#define LL 64
#define NHKD 16
#define QKV_CH 48

// scratch (device globals; no allocations)
__device__ __align__(16) float g_xh[BB*CC*LL];        // mean over W : [b][c][h]
__device__ __align__(16) float g_xw[BB*CC*LL];        // mean over H : [b][c][w]
__device__ __align__(16) float g_P[BB*CC*LL];         // (A*fs+fsh)*g*0.1
__device__ __align__(16) float g_Q[BB*CC*LL];         // (B*fs)*g*0.1

// ---------------------------------------------------------------------------
// K1: per-(b,c) 64x64 tile -> row means (over W) and col means (over H)
// (R8/R10 form — pinned by measurement)
// ---------------------------------------------------------------------------
__global__ void k1_reduce(const float* __restrict__ x) {
    int bc = blockIdx.x;                       // b*256 + c
    const float4* xt = (const float4*)(x + (size_t)bc * 4096);
    int t = threadIdx.x;                       // 256 threads
    __shared__ float scol[64];
    if (t < 64) scol[t] = 0.f;
    __syncthreads();

    float c0 = 0.f, c1 = 0.f, c2 = 0.f, c3 = 0.f;
    #pragma unroll
    for (int i = 0; i < 4; ++i) {
        int j = t + 256 * i;                   // float4 index in [0,1024)
        float4 v = xt[j];
        float rs = v.x + v.y + v.z + v.w;
        #pragma unroll
        for (int off = 8; off >= 1; off >>= 1)
            rs += __shfl_xor_sync(0xffffffffu, rs, off);
        if ((t & 15) == 0)
            g_xh[bc * 64 + (j >> 4)] = rs * (1.f / 64.f);
        c0 += v.x; c1 += v.y; c2 += v.z; c3 += v.w;
    }
    c0 += __shfl_xor_sync(0xffffffffu, c0, 16);
    c1 += __shfl_xor_sync(0xffffffffu, c1, 16);
    c2 += __shfl_xor_sync(0xffffffffu, c2, 16);
    c3 += __shfl_xor_sync(0xffffffffu, c3, 16);
    if ((t & 31) < 16) {
        int cb = (t & 15) * 4;
        atomicAdd(&scol[cb + 0], c0);
        atomicAdd(&scol[cb + 1], c1);
        atomicAdd(&scol[cb + 2], c2);
        atomicAdd(&scol[cb + 3], c3);
    }
    __syncthreads();
    if (t < 64) g_xw[bc * 64 + t] = scol[t] * (1.f / 64.f);
}

// ---------------------------------------------------------------------------
// K2345: qkv projection + axial attention + SE gate + P/Q, fused via a
// 2-CTA cluster. CTA pair = (b, axis=0) and (b, axis=1); the only cross-axis
// dependency (16 channel means each way) crosses via DSMEM st.shared::cluster.
// 64 blocks (b*2+axis), 256 threads. Static smem = 46.6 KB (< 48 KB).
// ---------------------------------------------------------------------------
__global__ void __cluster_dims__(2, 1, 1)
k2345_fused(const float* __restrict__ w_qkv,
            const float* __restrict__ qs,
            const float* __restrict__ qsh,
            const float* __restrict__ pos_h,
            const float* __restrict__ pos_w,
            const float* __restrict__ w_fusion,
            const float* __restrict__ fs,
            const float* __restrict__ fsh,
            const float* __restrict__ wg1,
            const float* __restrict__ g1s,
            const float* __restrict__ g1sh,
            const float* __restrict__ wg2,
            const float* __restrict__ g2s,
            const float* __restrict__ g2sh) {
    int blk  = blockIdx.x;         // b*2+axis in [0,64); cluster = {2b, 2b+1}
    int axis = blk & 1;            // == cluster ctarank
    int b    = blk >> 1;
    const float* xm = (axis == 0 ? g_xh : g_xw) + b * CC * 64;

    __shared__ __align__(16) float swT[64][QKV_CH];  // 12 KB [cl][o]
    __shared__ float sx[64][64];                     // 16 KB [c_local][l]
    __shared__ float sT[64][53];                     // 13.3 KB qkv^T [l][o]
    __shared__ __align__(16) float sM[NHKD][64];     // 4 KB attention out
    __shared__ float smeans[32];                     // both axes' means
    __shared__ float y[256];
    __shared__ float t1[64];

    int t  = threadIdx.x;
    int l  = t & 63;
    int og = t >> 6;                   // 4 o-groups of 12
    int lane = t & 31, wrp = t >> 5;

    // ---------------- phase A: qkv projection ----------------
    float acc[12];
    #pragma unroll
    for (int j = 0; j < 12; ++j) acc[j] = 0.f;

    for (int cc = 0; cc < 256; cc += 64) {
        for (int e = t; e < QKV_CH * 64; e += 256) {
            int o = e >> 6, cl = e & 63;
            swT[cl][o] = w_qkv[o * 256 + cc + cl];
        }
        for (int e = t; e < 64 * 64; e += 256) {
            int cl = e >> 6, ll = e & 63;
            sx[cl][ll] = xm[(cc + cl) * 64 + ll];
        }
        __syncthreads();
        const float4* swT4 = (const float4*)swT;     // 12 float4 per row
        #pragma unroll 4
        for (int cl = 0; cl < 64; ++cl) {
            float xv = sx[cl][l];
            float4 w0 = swT4[cl * 12 + og * 3 + 0];  // warp-uniform broadcast
            float4 w1 = swT4[cl * 12 + og * 3 + 1];
            float4 w2 = swT4[cl * 12 + og * 3 + 2];
            acc[0] += w0.x * xv; acc[1]  += w0.y * xv;
            acc[2] += w0.z * xv; acc[3]  += w0.w * xv;
            acc[4] += w1.x * xv; acc[5]  += w1.y * xv;
            acc[6] += w1.z * xv; acc[7]  += w1.w * xv;
            acc[8] += w2.x * xv; acc[9]  += w2.y * xv;
            acc[10]+= w2.z * xv; acc[11] += w2.w * xv;
        }
        __syncthreads();
    }

    const float* pos = axis ? pos_w : pos_h;
    #pragma unroll
    for (int j = 0; j < 12; ++j) {
        int o = og * 12 + j;
        float v = acc[j] * qs[o] + qsh[o];
        if (o < 32) v += pos[(o & 15) * 64 + l];   // pos added to q and k
        sT[l][o] = v;
    }
    __syncthreads();

    // ---------------- phase B: attention (threads 0..127) ----------------
    if (t < 128) {
        int i  = t & 63;
        int qo = (t >> 6) * 8;

        float qreg[8];
        #pragma unroll
        for (int d = 0; d < 8; ++d) qreg[d] = sT[i][qo + d];

        float a[64];
        float m = -1e30f;
        #pragma unroll
        for (int j = 0; j < 64; ++j) {
            float s = 0.f;
            #pragma unroll
            for (int d = 0; d < 8; ++d) s += qreg[d] * sT[j][16 + qo + d];
            s *= 0.35355339059327373f;  // 8^-0.5
            a[j] = s;
            m = fmaxf(m, s);
        }
        float ssum = 0.f;
        #pragma unroll
        for (int j = 0; j < 64; ++j) {
            float e = __expf(a[j] - m);
            a[j] = e;
            ssum += e;
        }
        float inv = 1.f / ssum;

        float acc2[8] = {0.f, 0.f, 0.f, 0.f, 0.f, 0.f, 0.f, 0.f};
        #pragma unroll
        for (int j = 0; j < 64; ++j) {
            float aj = a[j];
            #pragma unroll
            for (int d = 0; d < 8; ++d) acc2[d] += aj * sT[j][32 + qo + d];
        }
        #pragma unroll
        for (int d = 0; d < 8; ++d) sM[qo + d][i] = acc2[d] * inv;
    }
    __syncthreads();

    // ---------------- phase C: channel means + DSMEM exchange ----------------
    {
        int ch = t >> 4, sub = t & 15;          // 16 ch x 16 threads
        float s = 0.f;
        #pragma unroll
        for (int k = 0; k < 4; ++k) s += sM[ch][sub + 16 * k];
        #pragma unroll
        for (int off = 8; off >= 1; off >>= 1)
            s += __shfl_xor_sync(0xffffffffu, s, off);
        if (sub == 0) {
            float mv = s * (1.f / 64.f);
            int slot = axis * 16 + ch;
            smeans[slot] = mv;                  // local copy
            // remote copy into the peer CTA's smeans[slot]
            unsigned la = (unsigned)__cvta_generic_to_shared(&smeans[slot]);
            unsigned ra, peer = axis ^ 1;
            asm("mapa.shared::cluster.u32 %0, %1, %2;"
                : "=r"(ra) : "r"(la), "r"(peer));
            asm volatile("st.shared::cluster.f32 [%0], %1;"
                         :: "r"(ra), "f"(mv) : "memory");
        }
    }
    // cluster barrier: release own mean-store, acquire peer's
    asm volatile("barrier.cluster.arrive.aligned;" ::: "memory");
    asm volatile("barrier.cluster.wait.aligned;"   ::: "memory");

    // ---------------- phase D: gate chain (duplicated per CTA) ----------------
    // stage 2: y = cbn(w_fusion @ means)
    {
        const float4* wr = (const float4*)(w_fusion + t * 32);
        float s = 0.f;
        #pragma unroll
        for (int c4 = 0; c4 < 8; ++c4) {
            float4 wv = wr[c4];
            s += wv.x * smeans[c4 * 4 + 0] + wv.y * smeans[c4 * 4 + 1]
               + wv.z * smeans[c4 * 4 + 2] + wv.w * smeans[c4 * 4 + 3];
        }
        y[t] = s * fs[t] + fsh[t];
    }
    __syncthreads();

    // stage 3: t1 = silu(cbn(wg1 @ y)) — warp-per-row, coalesced lanes
    #pragma unroll
    for (int o = wrp; o < 64; o += 8) {
        const float* r = wg1 + o * 256;
        float s = 0.f;
        #pragma unroll
        for (int i = 0; i < 8; ++i) {
            int c = lane + 32 * i;
            s += r[c] * y[c];
        }
        #pragma unroll
        for (int off = 16; off >= 1; off >>= 1)
            s += __shfl_xor_sync(0xffffffffu, s, off);
        if (lane == 0) {
            s = s * g1s[o] + g1sh[o];
            t1[o] = s / (1.f + __expf(-s));
        }
    }
    __syncthreads();

    // stage 4: gate = sigmoid(cbn(wg2 @ t1))
    float gate;
    {
        const float4* wr = (const float4*)(wg2 + t * 64);
        float s = 0.f;
        #pragma unroll
        for (int c4 = 0; c4 < 16; ++c4) {
            float4 wv = wr[c4];
            s += wv.x * t1[c4 * 4 + 0] + wv.y * t1[c4 * 4 + 1]
               + wv.z * t1[c4 * 4 + 2] + wv.w * t1[c4 * 4 + 3];
        }
        s = s * g2s[t] + g2sh[t];
        gate = 1.f / (1.f + __expf(-s));
    }

    // ---------------- phase E: this axis' P or Q row for o = t ----------------
    int o = t;
    float scale = fs[o] * gate * 0.1f;
    float bias  = axis ? 0.f : fsh[o] * gate * 0.1f;
    float w[16];
    #pragma unroll
    for (int c = 0; c < 16; ++c) w[c] = w_fusion[o * 32 + axis * 16 + c];
    float* dst = (axis ? g_Q : g_P) + (b * 256 + o) * 64;
    const float4* base = (const float4*)sM;        // sM == this axis' attention

    #pragma unroll
    for (int lg = 0; lg < 16; ++lg) {
        float4 acc2 = {0.f, 0.f, 0.f, 0.f};
        #pragma unroll
        for (int c = 0; c < 16; ++c) {
            float4 xv = base[c * 16 + lg];     // warp-uniform broadcast
            acc2.x += w[c] * xv.x; acc2.y += w[c] * xv.y;
            acc2.z += w[c] * xv.z; acc2.w += w[c] * xv.w;
        }
        float4 r;
        r.x = acc2.x * scale + bias; r.y = acc2.y * scale + bias;
        r.z = acc2.z * scale + bias; r.w = acc2.w * scale + bias;
        ((float4*)dst)[lg] = r;
    }
}

// ---------------------------------------------------------------------------
// K6: out[b,o,h,w] = x + P[b,o,h] + Q[b,o,w].  8192 blocks, 256 threads.
// Reversed tile order (R10 win): re-read x where k1 left it hot in L2.
// ---------------------------------------------------------------------------
__global__ void k6_final(const float* __restrict__ x, float* __restrict__ out) {
    int blk = 8191 - blockIdx.x;       // reverse: b*256+o from the tail
    __shared__ float  sp[64];
    __shared__ float4 sq4[16];
    int t = threadIdx.x;
    if (t < 64) sp[t] = g_P[blk * 64 + t];
    else if (t < 80) sq4[t - 64] = ((const float4*)(g_Q + blk * 64))[t - 64];
    __syncthreads();

    const float4* xi = (const float4*)(x + (size_t)blk * 4096);
    float4*       xo = (float4*)(out + (size_t)blk * 4096);
    #pragma unroll
    for (int i = 0; i < 4; ++i) {
        int j = t + 256 * i;
        float  p  = sp[j >> 4];
        float4 qv = sq4[j & 15];
        float4 xv = xi[j];
        float4 r;
        r.x = xv.x + p + qv.x;
        r.y = xv.y + p + qv.y;
        r.z = xv.z + p + qv.z;
        r.w = xv.w + p + qv.w;
        xo[j] = r;
    }
}

// ---------------------------------------------------------------------------
// Input identification by element count (robust to metadata ordering).
// ---------------------------------------------------------------------------
extern "C" void kernel_launch(void* const* d_in, const int* in_sizes, int n_in,
                              void* d_out, int out_size) {
    const float *x = 0, *w_qkv = 0, *qkv_scale = 0, *qkv_shift = 0;
    const float *pos_h = 0, *pos_w = 0, *w_fusion = 0;
    const float *fusion_scale = 0, *fusion_shift = 0;
    const float *w_g1 = 0, *g1_scale = 0, *g1_shift = 0;
    const float *w_g2 = 0, *g2_scale = 0, *g2_shift = 0;

    int n48 = 0, n64 = 0, n256 = 0, n1024 = 0, n16384 = 0;
    for (int i = 0; i < n_in; ++i) {
        const float* p = (const float*)d_in[i];
        switch (in_sizes[i]) {
            case 33554432: x = p; break;
            case 12288:    w_qkv = p; break;
            case 8192:     w_fusion = p; break;
            case 48:
                if (n48++ == 0) qkv_scale = p; else qkv_shift = p; break;
            case 1024:
                if (n1024++ == 0) pos_h = p; else pos_w = p; break;
            case 16384:
                if (n16384++ == 0) w_g1 = p; else w_g2 = p; break;
            case 64:
                if (n64++ == 0) g1_scale = p; else g1_shift = p; break;
            case 256:
                switch (n256++) {
                    case 0: fusion_scale = p; break;
                    case 1: fusion_shift = p; break;
                    case 2: g2_scale = p; break;
                    default: g2_shift = p; break;
                }
                break;
            default: break;
        }
    }
    float* out = (float*)d_out;

    k1_reduce<<<BB * CC, 256>>>(x);
    k2345_fused<<<64, 256>>>(w_qkv, qkv_scale, qkv_shift, pos_h, pos_w,
                             w_fusion, fusion_scale, fusion_shift,
                             w_g1, g1_scale, g1_shift,
                             w_g2, g2_scale, g2_shift);
    k6_final<<<BB * CC, 256>>>(x, out);
}

// round 12
// speedup vs baseline: 1.0978x; 1.0174x over previous
#include <cuda_runtime.h>

#define BB 32
#define CC 256
#define LL 64
#define NHKD 16
#define QKV_CH 48

// scratch (device globals; no allocations)
__device__ __align__(16) float g_xh[BB*CC*LL];        // mean over W : [b][c][h]
__device__ __align__(16) float g_xw[BB*CC*LL];        // mean over H : [b][c][w]
__device__ __align__(16) float g_P[BB*CC*LL];         // (A*fs+fsh)*g*0.1
__device__ __align__(16) float g_Q[BB*CC*LL];         // (B*fs)*g*0.1

// ---------------------------------------------------------------------------
// K1: per-(b,c) 64x64 tile -> row means (over W) and col means (over H).
// Row reduction via smem transpose (srow[64][17], conflict-free) instead of
// 16 dependent SHFLs/thread — frees issue slots for the streaming loads.
// ---------------------------------------------------------------------------
__global__ void k1_reduce(const float* __restrict__ x) {
    int bc = blockIdx.x;                       // b*256 + c
    const float4* xt = (const float4*)(x + (size_t)bc * 4096);
    int t = threadIdx.x;                       // 256 threads
    __shared__ float scol[64];
    __shared__ float srow[64][17];             // padded: conflict-free
    if (t < 64) scol[t] = 0.f;
    __syncthreads();

    float c0 = 0.f, c1 = 0.f, c2 = 0.f, c3 = 0.f;
    #pragma unroll
    for (int i = 0; i < 4; ++i) {
        int j = t + 256 * i;                   // float4 index in [0,1024)
        float4 v = xt[j];
        srow[j >> 4][t & 15] = v.x + v.y + v.z + v.w;  // row partial
        c0 += v.x; c1 += v.y; c2 += v.z; c3 += v.w;    // col partials
    }
    c0 += __shfl_xor_sync(0xffffffffu, c0, 16);
    c1 += __shfl_xor_sync(0xffffffffu, c1, 16);
    c2 += __shfl_xor_sync(0xffffffffu, c2, 16);
    c3 += __shfl_xor_sync(0xffffffffu, c3, 16);
    if ((t & 31) < 16) {
        int cb = (t & 15) * 4;
        atomicAdd(&scol[cb + 0], c0);
        atomicAdd(&scol[cb + 1], c1);
        atomicAdd(&scol[cb + 2], c2);
        atomicAdd(&scol[cb + 3], c3);
    }
    __syncthreads();
    if (t < 64) {
        float s = 0.f;
        #pragma unroll
        for (int c = 0; c < 16; ++c) s += srow[t][c];
        g_xh[bc * 64 + t] = s * (1.f / 64.f);
        g_xw[bc * 64 + t] = scol[t] * (1.f / 64.f);
    }
}

// ---------------------------------------------------------------------------
// K2345: qkv projection + axial attention + SE gate + P/Q, fused via a
// 2-CTA cluster; cross-axis means exchanged through DSMEM.
// 64 blocks (b*2+axis), 256 threads.
// ---------------------------------------------------------------------------
__global__ void __cluster_dims__(2, 1, 1)
k2345_fused(const float* __restrict__ w_qkv,
            const float* __restrict__ qs,
            const float* __restrict__ qsh,
            const float* __restrict__ pos_h,
            const float* __restrict__ pos_w,
            const float* __restrict__ w_fusion,
            const float* __restrict__ fs,
            const float* __restrict__ fsh,
            const float* __restrict__ wg1,
            const float* __restrict__ g1s,
            const float* __restrict__ g1sh,
            const float* __restrict__ wg2,
            const float* __restrict__ g2s,
            const float* __restrict__ g2sh) {
    int blk  = blockIdx.x;         // b*2+axis in [0,64); cluster = {2b, 2b+1}
    int axis = blk & 1;            // == cluster ctarank
    int b    = blk >> 1;
    const float* xm = (axis == 0 ? g_xh : g_xw) + b * CC * 64;

    __shared__ __align__(16) float swT[64][QKV_CH];  // 12 KB [cl][o]
    __shared__ float sx[64][64];                     // 16 KB [c_local][l]
    __shared__ float sT[64][53];                     // 13.3 KB qkv^T [l][o]
    __shared__ __align__(16) float sM[NHKD][64];     // 4 KB attention out
    __shared__ float smeans[32];                     // both axes' means
    __shared__ float y[256];
    __shared__ float t1[64];

    int t  = threadIdx.x;
    int l  = t & 63;
    int og = t >> 6;                   // 4 o-groups of 12
    int lane = t & 31, wrp = t >> 5;

    // ---------------- phase A: qkv projection ----------------
    float acc[12];
    #pragma unroll
    for (int j = 0; j < 12; ++j) acc[j] = 0.f;

    for (int cc = 0; cc < 256; cc += 64) {
        for (int e = t; e < QKV_CH * 64; e += 256) {
            int o = e >> 6, cl = e & 63;
            swT[cl][o] = w_qkv[o * 256 + cc + cl];
        }
        for (int e = t; e < 64 * 64; e += 256) {
            int cl = e >> 6, ll = e & 63;
            sx[cl][ll] = xm[(cc + cl) * 64 + ll];
        }
        __syncthreads();
        const float4* swT4 = (const float4*)swT;     // 12 float4 per row
        #pragma unroll 4
        for (int cl = 0; cl < 64; ++cl) {
            float xv = sx[cl][l];
            float4 w0 = swT4[cl * 12 + og * 3 + 0];  // warp-uniform broadcast
            float4 w1 = swT4[cl * 12 + og * 3 + 1];
            float4 w2 = swT4[cl * 12 + og * 3 + 2];
            acc[0] += w0.x * xv; acc[1]  += w0.y * xv;
            acc[2] += w0.z * xv; acc[3]  += w0.w * xv;
            acc[4] += w1.x * xv; acc[5]  += w1.y * xv;
            acc[6] += w1.z * xv; acc[7]  += w1.w * xv;
            acc[8] += w2.x * xv; acc[9]  += w2.y * xv;
            acc[10]+= w2.z * xv; acc[11] += w2.w * xv;
        }
        __syncthreads();
    }

    const float* pos = axis ? pos_w : pos_h;
    #pragma unroll
    for (int j = 0; j < 12; ++j) {
        int o = og * 12 + j;
        float v = acc[j] * qs[o] + qsh[o];
        if (o < 32) v += pos[(o & 15) * 64 + l];   // pos added to q and k
        sT[l][o] = v;
    }
    __syncthreads();

    // ---------------- phase B: attention (threads 0..127) ----------------
    if (t < 128) {
        int i  = t & 63;
        int qo = (t >> 6) * 8;

        float qreg[8];
        #pragma unroll
        for (int d = 0; d < 8; ++d) qreg[d] = sT[i][qo + d];

        float a[64];
        float m = -1e30f;
        #pragma unroll
        for (int j = 0; j < 64; ++j) {
            float s = 0.f;
            #pragma unroll
            for (int d = 0; d < 8; ++d) s += qreg[d] * sT[j][16 + qo + d];
            s *= 0.35355339059327373f;  // 8^-0.5
            a[j] = s;
            m = fmaxf(m, s);
        }
        float ssum = 0.f;
        #pragma unroll
        for (int j = 0; j < 64; ++j) {
            float e = __expf(a[j] - m);
            a[j] = e;
            ssum += e;
        }
        float inv = 1.f / ssum;

        float acc2[8] = {0.f, 0.f, 0.f, 0.f, 0.f, 0.f, 0.f, 0.f};
        #pragma unroll
        for (int j = 0; j < 64; ++j) {
            float aj = a[j];
            #pragma unroll
            for (int d = 0; d < 8; ++d) acc2[d] += aj * sT[j][32 + qo + d];
        }
        #pragma unroll
        for (int d = 0; d < 8; ++d) sM[qo + d][i] = acc2[d] * inv;
    }
    __syncthreads();

    // ---- prefetch this thread's w_fusion row (overlaps barrier wait) ----
    float4 wf[8];
    {
        const float4* wr = (const float4*)(w_fusion + t * 32);
        #pragma unroll
        for (int i = 0; i < 8; ++i) wf[i] = wr[i];
    }

    // ---------------- phase C: channel means + DSMEM exchange ----------------
    {
        int ch = t >> 4, sub = t & 15;          // 16 ch x 16 threads
        float s = 0.f;
        #pragma unroll
        for (int k = 0; k < 4; ++k) s += sM[ch][sub + 16 * k];
        #pragma unroll
        for (int off = 8; off >= 1; off >>= 1)
            s += __shfl_xor_sync(0xffffffffu, s, off);
        if (sub == 0) {
            float mv = s * (1.f / 64.f);
            int slot = axis * 16 + ch;
            smeans[slot] = mv;                  // local copy
            // remote copy into the peer CTA's smeans[slot]
            unsigned la = (unsigned)__cvta_generic_to_shared(&smeans[slot]);
            unsigned ra, peer = axis ^ 1;
            asm("mapa.shared::cluster.u32 %0, %1, %2;"
                : "=r"(ra) : "r"(la), "r"(peer));
            asm volatile("st.shared::cluster.f32 [%0], %1;"
                         :: "r"(ra), "f"(mv) : "memory");
        }
    }
    // cluster barrier: release own mean-store, acquire peer's
    asm volatile("barrier.cluster.arrive.aligned;" ::: "memory");
    asm volatile("barrier.cluster.wait.aligned;"   ::: "memory");

    // ---------------- phase D: gate chain (duplicated per CTA) ----------------
    // stage 2: y = cbn(w_fusion @ means)  (weights already in registers)
    {
        float s = 0.f;
        #pragma unroll
        for (int c4 = 0; c4 < 8; ++c4) {
            float4 wv = wf[c4];
            s += wv.x * smeans[c4 * 4 + 0] + wv.y * smeans[c4 * 4 + 1]
               + wv.z * smeans[c4 * 4 + 2] + wv.w * smeans[c4 * 4 + 3];
        }
        y[t] = s * fs[t] + fsh[t];
    }
    __syncthreads();

    // stage 3: t1 = silu(cbn(wg1 @ y)) — warp-per-row, coalesced lanes
    #pragma unroll
    for (int o = wrp; o < 64; o += 8) {
        const float* r = wg1 + o * 256;
        float s = 0.f;
        #pragma unroll
        for (int i = 0; i < 8; ++i) {
            int c = lane + 32 * i;
            s += r[c] * y[c];
        }
        #pragma unroll
        for (int off = 16; off >= 1; off >>= 1)
            s += __shfl_xor_sync(0xffffffffu, s, off);
        if (lane == 0) {
            s = s * g1s[o] + g1sh[o];
            t1[o] = s / (1.f + __expf(-s));
        }
    }
    __syncthreads();

    // stage 4: gate = sigmoid(cbn(wg2 @ t1))
    float gate;
    {
        const float4* wr = (const float4*)(wg2 + t * 64);
        float s = 0.f;
        #pragma unroll
        for (int c4 = 0; c4 < 16; ++c4) {
            float4 wv = wr[c4];
            s += wv.x * t1[c4 * 4 + 0] + wv.y * t1[c4 * 4 + 1]
               + wv.z * t1[c4 * 4 + 2] + wv.w * t1[c4 * 4 + 3];
        }
        s = s * g2s[t] + g2sh[t];
        gate = 1.f / (1.f + __expf(-s));
    }

    // ---------------- phase E: this axis' P or Q row for o = t ----------------
    int o = t;
    float scale = fs[o] * gate * 0.1f;
    float bias  = axis ? 0.f : fsh[o] * gate * 0.1f;
    float w[16];
    const float* wff = (const float*)wf;
    if (axis == 0) {
        #pragma unroll
        for (int c = 0; c < 16; ++c) w[c] = wff[c];
    } else {
        #pragma unroll
        for (int c = 0; c < 16; ++c) w[c] = wff[16 + c];
    }
    float* dst = (axis ? g_Q : g_P) + (b * 256 + o) * 64;
    const float4* base = (const float4*)sM;        // sM == this axis' attention

    #pragma unroll
    for (int lg = 0; lg < 16; ++lg) {
        float4 acc2 = {0.f, 0.f, 0.f, 0.f};
        #pragma unroll
        for (int c = 0; c < 16; ++c) {
            float4 xv = base[c * 16 + lg];     // warp-uniform broadcast
            acc2.x += w[c] * xv.x; acc2.y += w[c] * xv.y;
            acc2.z += w[c] * xv.z; acc2.w += w[c] * xv.w;
        }
        float4 r;
        r.x = acc2.x * scale + bias; r.y = acc2.y * scale + bias;
        r.z = acc2.z * scale + bias; r.w = acc2.w * scale + bias;
        ((float4*)dst)[lg] = r;
    }
}

// ---------------------------------------------------------------------------
// K6: out[b,o,h,w] = x + P[b,o,h] + Q[b,o,w].  8192 blocks, 256 threads.
// Reversed tile order (R10 win). __stcs on stores ONLY: evict-first for the
// single-touch out stream, preserving L2 residency for the x re-reads.
// ---------------------------------------------------------------------------
__global__ void k6_final(const float* __restrict__ x, float* __restrict__ out) {
    int blk = 8191 - blockIdx.x;       // reverse: b*256+o from the tail
    __shared__ float  sp[64];
    __shared__ float4 sq4[16];
    int t = threadIdx.x;
    if (t < 64) sp[t] = g_P[blk * 64 + t];
    else if (t < 80) sq4[t - 64] = ((const float4*)(g_Q + blk * 64))[t - 64];
    __syncthreads();

    const float4* xi = (const float4*)(x + (size_t)blk * 4096);
    float4*       xo = (float4*)(out + (size_t)blk * 4096);
    #pragma unroll
    for (int i = 0; i < 4; ++i) {
        int j = t + 256 * i;
        float  p  = sp[j >> 4];
        float4 qv = sq4[j & 15];
        float4 xv = xi[j];
        float4 r;
        r.x = xv.x + p + qv.x;
        r.y = xv.y + p + qv.y;
        r.z = xv.z + p + qv.z;
        r.w = xv.w + p + qv.w;
        __stcs(xo + j, r);
    }
}

// ---------------------------------------------------------------------------
// Input identification by element count (robust to metadata ordering).
// ---------------------------------------------------------------------------
extern "C" void kernel_launch(void* const* d_in, const int* in_sizes, int n_in,
                              void* d_out, int out_size) {
    const float *x = 0, *w_qkv = 0, *qkv_scale = 0, *qkv_shift = 0;
    const float *pos_h = 0, *pos_w = 0, *w_fusion = 0;
    const float *fusion_scale = 0, *fusion_shift = 0;
    const float *w_g1 = 0, *g1_scale = 0, *g1_shift = 0;
    const float *w_g2 = 0, *g2_scale = 0, *g2_shift = 0;

    int n48 = 0, n64 = 0, n256 = 0, n1024 = 0, n16384 = 0;
    for (int i = 0; i < n_in; ++i) {
        const float* p = (const float*)d_in[i];
        switch (in_sizes[i]) {
            case 33554432: x = p; break;
            case 12288:    w_qkv = p; break;
            case 8192:     w_fusion = p; break;
            case 48:
                if (n48++ == 0) qkv_scale = p; else qkv_shift = p; break;
            case 1024:
                if (n1024++ == 0) pos_h = p; else pos_w = p; break;
            case 16384:
                if (n16384++ == 0) w_g1 = p; else w_g2 = p; break;
            case 64:
                if (n64++ == 0) g1_scale = p; else g1_shift = p; break;
            case 256:
                switch (n256++) {
                    case 0: fusion_scale = p; break;
                    case 1: fusion_shift = p; break;
                    case 2: g2_scale = p; break;
                    default: g2_shift = p; break;
                }
                break;
            default: break;
        }
    }
    float* out = (float*)d_out;

    k1_reduce<<<BB * CC, 256>>>(x);
    k2345_fused<<<64, 256>>>(w_qkv, qkv_scale, qkv_shift, pos_h, pos_w,
                             w_fusion, fusion_scale, fusion_shift,
                             w_g1, g1_scale, g1_shift,
                             w_g2, g2_scale, g2_shift);
    k6_final<<<BB * CC, 256>>>(x, out);
}